// round 1
// baseline (speedup 1.0000x reference)
#include <cuda_runtime.h>
#include <math.h>

// ---------------------------------------------------------------------------
// SwinLayer: B=2, C=192, NH=6, HD=32, D=16,H=32,W=32, window (4,8,8), L=256
// DEPTH=2 (layer 0 unshifted, layer 1 shifted by (2,4,4)), HID=768
// ---------------------------------------------------------------------------

#define NTOK 32768      // B*D*H*W
#define CCH 192
#define NQKV 576
#define HIDN 768
#define NWIN 128        // total windows (B * 64)
#define LWIN 256
#define NHD 6
#define HDD 32
#define ASCALE 0.17677669529663687f  // 32^-0.5

// Scratch (device globals: allocation-free rule)
__device__ float g_X [NTOK*CCH];     // token-major residual stream
__device__ float g_Hb[NTOK*CCH];     // LN1 out, window-major
__device__ float g_QKV[NTOK*NQKV];   // window-major
__device__ float g_O [NTOK*CCH];     // attn out, window-major
__device__ float g_P [NTOK*CCH];     // proj out, window-major
__device__ float g_H2[NTOK*CCH];     // LN2 out, token-major
__device__ float g_M [NTOK*HIDN];    // FC1 out
__device__ float g_biasT[2*NHD*LWIN*LWIN];  // [layer][head][k*256+p]

// window-token -> original token index (applies inverse shift when shifted)
__device__ __forceinline__ int wt_to_src(int wt, int shifted) {
    int n = wt >> 8, p = wt & 255;
    int bb = n >> 6, r = n & 63;
    int gd = ((r >> 4) << 2) + (p >> 6);
    int gh = (((r >> 2) & 3) << 3) + ((p >> 3) & 7);
    int gw = ((r & 3) << 3) + (p & 7);
    if (shifted) { gd = (gd + 14) & 15; gh = (gh + 28) & 31; gw = (gw + 28) & 31; }
    return ((bb * 16 + gd) * 32 + gh) * 32 + gw;
}

// ---------------------------------------------------------------------------
// (B,C,S) -> (B,S,C) tiled transpose.   S = 16384 spatial
// ---------------------------------------------------------------------------
__global__ void transpose_in(const float* __restrict__ x, float* __restrict__ X) {
    __shared__ float t[32][33];
    int b = blockIdx.z;
    int s0 = blockIdx.x * 32, c0 = blockIdx.y * 32;
    // read coalesced along s
    t[threadIdx.y][threadIdx.x] =
        x[((size_t)(b * CCH + c0 + threadIdx.y)) * 16384 + s0 + threadIdx.x];
    __syncthreads();
    // write coalesced along c
    X[((size_t)(b * 16384 + s0 + threadIdx.y)) * CCH + c0 + threadIdx.x] =
        t[threadIdx.x][threadIdx.y];
}

__global__ void transpose_out(const float* __restrict__ X, float* __restrict__ out) {
    __shared__ float t[32][33];
    int b = blockIdx.z;
    int s0 = blockIdx.x * 32, c0 = blockIdx.y * 32;
    // read coalesced along c
    t[threadIdx.y][threadIdx.x] =
        X[((size_t)(b * 16384 + s0 + threadIdx.y)) * CCH + c0 + threadIdx.x];
    __syncthreads();
    // write coalesced along s
    out[((size_t)(b * CCH + c0 + threadIdx.y)) * 16384 + s0 + threadIdx.x] =
        t[threadIdx.x][threadIdx.y];
}

// ---------------------------------------------------------------------------
// Pre-gather relative position bias, TRANSPOSED: biasT[l][h][k*256+p]
// ---------------------------------------------------------------------------
__global__ void bias_gather(const float* __restrict__ rpb, const int* __restrict__ rpi,
                            float* __restrict__ biasT) {
    int idx = blockIdx.x * 256 + threadIdx.x;     // 2*6*65536 = 786432
    if (idx >= 2 * NHD * 65536) return;
    int lh = idx >> 16;          // layer*6 + head
    int kk = idx & 65535;        // k*256 + p
    int p = kk & 255, k = kk >> 8;
    biasT[idx] = rpb[lh * 1575 + rpi[p * 256 + k]];
}

// ---------------------------------------------------------------------------
// LayerNorm. mode 0: token-major identity; 1: gather to window-major;
//            2: gather to window-major with shift.
// One warp per token, 192 channels = 6/lane.
// ---------------------------------------------------------------------------
__global__ __launch_bounds__(256) void ln_kernel(
    const float* __restrict__ X, const float* __restrict__ w,
    const float* __restrict__ b, float* __restrict__ Out, int mode) {
    int warp = threadIdx.x >> 5, lane = threadIdx.x & 31;
    int wt = blockIdx.x * 8 + warp;
    int src = (mode == 0) ? wt : wt_to_src(wt, mode == 2);
    const float* xp = X + (size_t)src * CCH;
    float v[6];
    float s = 0.f;
#pragma unroll
    for (int i = 0; i < 6; i++) { v[i] = xp[lane + 32 * i]; s += v[i]; }
#pragma unroll
    for (int off = 16; off > 0; off >>= 1) s += __shfl_xor_sync(0xffffffffu, s, off);
    float mu = s * (1.f / CCH);
    float s2 = 0.f;
#pragma unroll
    for (int i = 0; i < 6; i++) { float d = v[i] - mu; s2 += d * d; }
#pragma unroll
    for (int off = 16; off > 0; off >>= 1) s2 += __shfl_xor_sync(0xffffffffu, s2, off);
    float inv = rsqrtf(s2 * (1.f / CCH) + 1e-5f);
    float* op = Out + (size_t)wt * CCH;
#pragma unroll
    for (int i = 0; i < 6; i++) {
        int c = lane + 32 * i;
        op[c] = (v[i] - mu) * inv * w[c] + b[c];
    }
}

// ---------------------------------------------------------------------------
// GEMM: C[M,N] = A[M,K] @ W[N,K]^T + bias ; epilogues.
// EPI 0: plain. 1: exact GELU. 2: + Res (residual add).
// 64x64x16 tile, 256 threads, 4x4 per thread, float4 everywhere.
// ---------------------------------------------------------------------------
template <int EPI>
__global__ __launch_bounds__(256) void gemm_kernel(
    const float* __restrict__ A, const float* __restrict__ W,
    const float* __restrict__ bias, const float* __restrict__ Res,
    float* __restrict__ C, int M, int N, int K) {
    __shared__ float As[16][64];
    __shared__ float Ws[16][64];
    int tid = threadIdx.x;
    int tx = tid & 15, ty = tid >> 4;
    int bm = blockIdx.y * 64, bn = blockIdx.x * 64;
    int lr = tid >> 2;    // 0..63
    int lq = tid & 3;     // float4 slot along K
    float acc[4][4] = {};
    for (int k0 = 0; k0 < K; k0 += 16) {
        float4 av = *(const float4*)&A[(size_t)(bm + lr) * K + k0 + lq * 4];
        float4 wv = *(const float4*)&W[(size_t)(bn + lr) * K + k0 + lq * 4];
        As[lq * 4 + 0][lr] = av.x; As[lq * 4 + 1][lr] = av.y;
        As[lq * 4 + 2][lr] = av.z; As[lq * 4 + 3][lr] = av.w;
        Ws[lq * 4 + 0][lr] = wv.x; Ws[lq * 4 + 1][lr] = wv.y;
        Ws[lq * 4 + 2][lr] = wv.z; Ws[lq * 4 + 3][lr] = wv.w;
        __syncthreads();
#pragma unroll
        for (int kk = 0; kk < 16; kk++) {
            float4 a4 = *(const float4*)&As[kk][ty * 4];
            float4 b4 = *(const float4*)&Ws[kk][tx * 4];
            float a[4] = {a4.x, a4.y, a4.z, a4.w};
            float bb[4] = {b4.x, b4.y, b4.z, b4.w};
#pragma unroll
            for (int i = 0; i < 4; i++)
#pragma unroll
                for (int j = 0; j < 4; j++) acc[i][j] += a[i] * bb[j];
        }
        __syncthreads();
    }
#pragma unroll
    for (int i = 0; i < 4; i++) {
        int row = bm + ty * 4 + i;
#pragma unroll
        for (int j = 0; j < 4; j++) {
            int col = bn + tx * 4 + j;
            float v = acc[i][j] + bias[col];
            if (EPI == 1) v = 0.5f * v * (1.f + erff(v * 0.70710678118654752f));
            if (EPI == 2) v += Res[(size_t)row * N + col];
            C[(size_t)row * N + col] = v;
        }
    }
}

// ---------------------------------------------------------------------------
// Attention per (window, head). One thread = one query row, flash-style
// online softmax with rare rescale. K/V staged in 64KB dynamic smem.
// biasT read coalesced: biasT[h][k*256 + p]. Shift mask recomputed from labels.
// ---------------------------------------------------------------------------
__global__ __launch_bounds__(256) void attn_kernel(
    const float* __restrict__ QKV, const float* __restrict__ biasT,
    float* __restrict__ O, int shifted) {
    extern __shared__ float sm[];
    float* Ks = sm;
    float* Vs = sm + LWIN * HDD;
    unsigned char* lbl = (unsigned char*)(Vs + LWIN * HDD);
    int n = blockIdx.x, h = blockIdx.y;
    int tid = threadIdx.x;
    {
        int r0 = tid >> 5, d = tid & 31;
        for (int pass = 0; pass < 32; pass++) {
            int r = (pass << 3) + r0;
            size_t base = (size_t)((n << 8) + r) * NQKV + h * HDD;
            Ks[r * HDD + d] = QKV[base + CCH + d];
            Vs[r * HDD + d] = QKV[base + 2 * CCH + d];
        }
    }
    int p = tid;
    if (shifted) {
        int rr = n & 63;
        int gd = ((rr >> 4) << 2) + (p >> 6);
        int gh = (((rr >> 2) & 3) << 3) + ((p >> 3) & 7);
        int gw = ((rr & 3) << 3) + (p & 7);
        lbl[p] = (unsigned char)(((gd < 2) ? 4 : 0) + ((gh < 4) ? 2 : 0) + ((gw < 4) ? 1 : 0));
    }
    __syncthreads();
    float q[HDD];
    {
        const float4* qp = (const float4*)(QKV + (size_t)((n << 8) + p) * NQKV + h * HDD);
#pragma unroll
        for (int i = 0; i < 8; i++) {
            float4 v = qp[i];
            q[i * 4] = v.x; q[i * 4 + 1] = v.y; q[i * 4 + 2] = v.z; q[i * 4 + 3] = v.w;
        }
    }
    float o[HDD];
#pragma unroll
    for (int d = 0; d < HDD; d++) o[d] = 0.f;
    float m = -3.0e38f, l = 0.f;
    const float* bT = biasT + (h << 16) + p;
    int myl = shifted ? (int)lbl[p] : 0;
    for (int k = 0; k < LWIN; k++) {
        if (shifted && (int)lbl[k] != myl) continue;   // exact exp(-inf)=0
        const float* kr = Ks + k * HDD;
        float s = 0.f;
#pragma unroll
        for (int d = 0; d < HDD; d++) s += q[d] * kr[d];
        s = s * ASCALE + bT[k << 8];
        const float* vr = Vs + k * HDD;
        if (s <= m) {
            float px = __expf(s - m);
            l += px;
#pragma unroll
            for (int d = 0; d < HDD; d++) o[d] += px * vr[d];
        } else {
            float c = __expf(m - s);    // first hit: exp(-inf)=0, clean start
            l = l * c + 1.f;
#pragma unroll
            for (int d = 0; d < HDD; d++) o[d] = o[d] * c + vr[d];
            m = s;
        }
    }
    float inv = 1.f / l;
    float4* op = (float4*)(O + (size_t)((n << 8) + p) * CCH + h * HDD);
#pragma unroll
    for (int i = 0; i < 8; i++) {
        float4 v;
        v.x = o[i * 4] * inv; v.y = o[i * 4 + 1] * inv;
        v.z = o[i * 4 + 2] * inv; v.w = o[i * 4 + 3] * inv;
        op[i] = v;
    }
}

// ---------------------------------------------------------------------------
// Scatter proj output back to token-major with inverse shift, add residual.
// ---------------------------------------------------------------------------
__global__ __launch_bounds__(256) void scatter_add(
    const float* __restrict__ P, float* __restrict__ X, int shifted) {
    int idx = blockIdx.x * 256 + threadIdx.x;  // NTOK*CCH
    int wt = idx / CCH, c = idx - wt * CCH;
    int src = wt_to_src(wt, shifted);
    X[(size_t)src * CCH + c] += P[idx];
}

// ---------------------------------------------------------------------------
extern "C" void kernel_launch(void* const* d_in, const int* in_sizes, int n_in,
                              void* d_out, int out_size) {
    const float* x      = (const float*)d_in[0];
    const float* ln1_w  = (const float*)d_in[1];
    const float* ln1_b  = (const float*)d_in[2];
    const float* qkv_w  = (const float*)d_in[3];
    const float* qkv_b  = (const float*)d_in[4];
    const float* rpb    = (const float*)d_in[5];
    const float* proj_w = (const float*)d_in[6];
    const float* proj_b = (const float*)d_in[7];
    const float* ln2_w  = (const float*)d_in[8];
    const float* ln2_b  = (const float*)d_in[9];
    const float* fc1_w  = (const float*)d_in[10];
    const float* fc1_b  = (const float*)d_in[11];
    const float* fc2_w  = (const float*)d_in[12];
    const float* fc2_b  = (const float*)d_in[13];
    const int*   rpi    = (const int*)d_in[14];
    float* out = (float*)d_out;

    float *pX, *pH, *pQ, *pO, *pP, *pH2, *pM, *pB;
    cudaGetSymbolAddress((void**)&pX,  g_X);
    cudaGetSymbolAddress((void**)&pH,  g_Hb);
    cudaGetSymbolAddress((void**)&pQ,  g_QKV);
    cudaGetSymbolAddress((void**)&pO,  g_O);
    cudaGetSymbolAddress((void**)&pP,  g_P);
    cudaGetSymbolAddress((void**)&pH2, g_H2);
    cudaGetSymbolAddress((void**)&pM,  g_M);
    cudaGetSymbolAddress((void**)&pB,  g_biasT);

    const int ATTN_SMEM = 2 * LWIN * HDD * 4 + LWIN;  // 65792
    cudaFuncSetAttribute(attn_kernel, cudaFuncAttributeMaxDynamicSharedMemorySize,
                         ATTN_SMEM);

    dim3 tpb(32, 32);
    transpose_in<<<dim3(512, 6, 2), tpb>>>(x, pX);
    bias_gather<<<(2 * NHD * 65536) / 256, 256>>>(rpb, rpi, pB);

    for (int i = 0; i < 2; i++) {
        int sh = i;  // layer 1 shifted
        ln_kernel<<<NTOK / 8, 256>>>(pX, ln1_w + i * CCH, ln1_b + i * CCH, pH, sh ? 2 : 1);
        gemm_kernel<0><<<dim3(NQKV / 64, NTOK / 64), 256>>>(
            pH, qkv_w + (size_t)i * NQKV * CCH, qkv_b + i * NQKV, nullptr, pQ,
            NTOK, NQKV, CCH);
        attn_kernel<<<dim3(NWIN, NHD), 256, ATTN_SMEM>>>(
            pQ, pB + (size_t)i * NHD * 65536, pO, sh);
        gemm_kernel<0><<<dim3(CCH / 64, NTOK / 64), 256>>>(
            pO, proj_w + (size_t)i * CCH * CCH, proj_b + i * CCH, nullptr, pP,
            NTOK, CCH, CCH);
        scatter_add<<<(NTOK * CCH) / 256, 256>>>(pP, pX, sh);
        ln_kernel<<<NTOK / 8, 256>>>(pX, ln2_w + i * CCH, ln2_b + i * CCH, pH2, 0);
        gemm_kernel<1><<<dim3(HIDN / 64, NTOK / 64), 256>>>(
            pH2, fc1_w + (size_t)i * HIDN * CCH, fc1_b + i * HIDN, nullptr, pM,
            NTOK, HIDN, CCH);
        gemm_kernel<2><<<dim3(CCH / 64, NTOK / 64), 256>>>(
            pM, fc2_w + (size_t)i * CCH * HIDN, fc2_b + i * CCH, pX, pX,
            NTOK, CCH, HIDN);
    }
    transpose_out<<<dim3(512, 6, 2), tpb>>>(pX, out);
}

// round 2
// speedup vs baseline: 1.0407x; 1.0407x over previous
#include <cuda_runtime.h>
#include <math.h>

// ---------------------------------------------------------------------------
// SwinLayer: B=2, C=192, NH=6, HD=32, D=16,H=32,W=32, window (4,8,8), L=256
// DEPTH=2 (layer 0 unshifted, layer 1 shifted by (2,4,4)), HID=768
// ---------------------------------------------------------------------------

#define NTOK 32768      // B*D*H*W
#define CCH 192
#define NQKV 576
#define HIDN 768
#define NWIN 128        // total windows (B * 64)
#define LWIN 256
#define NHD 6
#define HDD 32
#define ASCALE 0.17677669529663687f  // 32^-0.5

// Scratch (device globals: allocation-free rule)
__device__ float g_X [NTOK*CCH];     // token-major residual stream
__device__ float g_Hb[NTOK*CCH];     // LN1 out, window-major
__device__ float g_QKV[NTOK*NQKV];   // window-major
__device__ float g_O [NTOK*CCH];     // attn out, window-major
__device__ float g_P [NTOK*CCH];     // proj out, window-major
__device__ float g_H2[NTOK*CCH];     // LN2 out, token-major
__device__ float g_M [NTOK*HIDN];    // FC1 out
__device__ float g_biasT[2*NHD*LWIN*LWIN];  // [layer][head][k*256+p]

// window-token -> original token index (applies inverse shift when shifted)
__device__ __forceinline__ int wt_to_src(int wt, int shifted) {
    int n = wt >> 8, p = wt & 255;
    int bb = n >> 6, r = n & 63;
    int gd = ((r >> 4) << 2) + (p >> 6);
    int gh = (((r >> 2) & 3) << 3) + ((p >> 3) & 7);
    int gw = ((r & 3) << 3) + (p & 7);
    if (shifted) { gd = (gd + 14) & 15; gh = (gh + 28) & 31; gw = (gw + 28) & 31; }
    return ((bb * 16 + gd) * 32 + gh) * 32 + gw;
}

// ---------------------------------------------------------------------------
// (B,C,S) -> (B,S,C) tiled transpose.   S = 16384 spatial
// ---------------------------------------------------------------------------
__global__ void transpose_in(const float* __restrict__ x, float* __restrict__ X) {
    __shared__ float t[32][33];
    int b = blockIdx.z;
    int s0 = blockIdx.x * 32, c0 = blockIdx.y * 32;
    t[threadIdx.y][threadIdx.x] =
        x[((size_t)(b * CCH + c0 + threadIdx.y)) * 16384 + s0 + threadIdx.x];
    __syncthreads();
    X[((size_t)(b * 16384 + s0 + threadIdx.y)) * CCH + c0 + threadIdx.x] =
        t[threadIdx.x][threadIdx.y];
}

__global__ void transpose_out(const float* __restrict__ X, float* __restrict__ out) {
    __shared__ float t[32][33];
    int b = blockIdx.z;
    int s0 = blockIdx.x * 32, c0 = blockIdx.y * 32;
    t[threadIdx.y][threadIdx.x] =
        X[((size_t)(b * 16384 + s0 + threadIdx.y)) * CCH + c0 + threadIdx.x];
    __syncthreads();
    out[((size_t)(b * CCH + c0 + threadIdx.y)) * 16384 + s0 + threadIdx.x] =
        t[threadIdx.x][threadIdx.y];
}

// ---------------------------------------------------------------------------
// Pre-gather relative position bias, TRANSPOSED: biasT[l][h][k*256+p]
// ---------------------------------------------------------------------------
__global__ void bias_gather(const float* __restrict__ rpb, const int* __restrict__ rpi,
                            float* __restrict__ biasT) {
    int idx = blockIdx.x * 256 + threadIdx.x;     // 2*6*65536 = 786432
    if (idx >= 2 * NHD * 65536) return;
    int lh = idx >> 16;          // layer*6 + head
    int kk = idx & 65535;        // k*256 + p
    int p = kk & 255, k = kk >> 8;
    biasT[idx] = rpb[lh * 1575 + rpi[p * 256 + k]];
}

// ---------------------------------------------------------------------------
// LayerNorm. mode 0: token-major identity; 1: gather to window-major;
//            2: gather to window-major with shift.
// ---------------------------------------------------------------------------
__global__ __launch_bounds__(256) void ln_kernel(
    const float* __restrict__ X, const float* __restrict__ w,
    const float* __restrict__ b, float* __restrict__ Out, int mode) {
    int warp = threadIdx.x >> 5, lane = threadIdx.x & 31;
    int wt = blockIdx.x * 8 + warp;
    int src = (mode == 0) ? wt : wt_to_src(wt, mode == 2);
    const float* xp = X + (size_t)src * CCH;
    float v[6];
    float s = 0.f;
#pragma unroll
    for (int i = 0; i < 6; i++) { v[i] = xp[lane + 32 * i]; s += v[i]; }
#pragma unroll
    for (int off = 16; off > 0; off >>= 1) s += __shfl_xor_sync(0xffffffffu, s, off);
    float mu = s * (1.f / CCH);
    float s2 = 0.f;
#pragma unroll
    for (int i = 0; i < 6; i++) { float d = v[i] - mu; s2 += d * d; }
#pragma unroll
    for (int off = 16; off > 0; off >>= 1) s2 += __shfl_xor_sync(0xffffffffu, s2, off);
    float inv = rsqrtf(s2 * (1.f / CCH) + 1e-5f);
    float* op = Out + (size_t)wt * CCH;
#pragma unroll
    for (int i = 0; i < 6; i++) {
        int c = lane + 32 * i;
        op[c] = (v[i] - mu) * inv * w[c] + b[c];
    }
}

// ---------------------------------------------------------------------------
// GEMM: C[M,N] = A[M,K] @ W[N,K]^T + bias ; epilogues.
// EPI 0: plain. 1: exact GELU. 2: + Res (residual add).
// 128x64x16 tile, 128 threads, 8x8 microtile, double-buffered smem.
// Per warp-kk: 4 LDS128 (16 SM-cyc) vs 64 FFMA (32 SM-cyc) -> FFMA-bound.
// Smem fill: lanes write consecutive rows -> conflict-free.
// ---------------------------------------------------------------------------
template <int EPI>
__global__ __launch_bounds__(128) void gemm_kernel(
    const float* __restrict__ A, const float* __restrict__ W,
    const float* __restrict__ bias, const float* __restrict__ Res,
    float* __restrict__ C, int M, int N, int K) {
    __shared__ float As[2][16][128];
    __shared__ float Bs[2][16][64];
    int tid = threadIdx.x;
    int tx = tid & 7;        // N microtile (0..7)
    int ty = tid >> 3;       // M microtile (0..15)
    int bm = blockIdx.y * 128, bn = blockIdx.x * 64;

    const float* Arow = A + (size_t)(bm + tid) * K;   // 1 row per thread
    int bcol0 = tid & 63, bq0 = tid >> 6;             // B load slot 0
    int bcol1 = (tid + 128) & 63, bq1 = (tid + 128) >> 6;
    const float* Wr0 = W + (size_t)(bn + bcol0) * K;
    const float* Wr1 = W + (size_t)(bn + bcol1) * K;

    float4 aR[4];
    float4 bR[2];

    // --- prologue: load chunk 0 ---
#pragma unroll
    for (int q = 0; q < 4; q++) aR[q] = *(const float4*)&Arow[q * 4];
    bR[0] = *(const float4*)&Wr0[bq0 * 4];
    bR[1] = *(const float4*)&Wr1[bq1 * 4];
#pragma unroll
    for (int q = 0; q < 4; q++) {
        As[0][q * 4 + 0][tid] = aR[q].x; As[0][q * 4 + 1][tid] = aR[q].y;
        As[0][q * 4 + 2][tid] = aR[q].z; As[0][q * 4 + 3][tid] = aR[q].w;
    }
    Bs[0][bq0 * 4 + 0][bcol0] = bR[0].x; Bs[0][bq0 * 4 + 1][bcol0] = bR[0].y;
    Bs[0][bq0 * 4 + 2][bcol0] = bR[0].z; Bs[0][bq0 * 4 + 3][bcol0] = bR[0].w;
    Bs[0][bq1 * 4 + 0][bcol1] = bR[1].x; Bs[0][bq1 * 4 + 1][bcol1] = bR[1].y;
    Bs[0][bq1 * 4 + 2][bcol1] = bR[1].z; Bs[0][bq1 * 4 + 3][bcol1] = bR[1].w;
    __syncthreads();

    float acc[8][8] = {};
    int nk = K >> 4;
    for (int kt = 0; kt < nk; kt++) {
        int buf = kt & 1;
        if (kt + 1 < nk) {       // issue next-chunk global loads early
            int k0 = (kt + 1) << 4;
#pragma unroll
            for (int q = 0; q < 4; q++) aR[q] = *(const float4*)&Arow[k0 + q * 4];
            bR[0] = *(const float4*)&Wr0[k0 + bq0 * 4];
            bR[1] = *(const float4*)&Wr1[k0 + bq1 * 4];
        }
#pragma unroll
        for (int kk = 0; kk < 16; kk++) {
            float a[8], b[8];
            *(float4*)&a[0] = *(const float4*)&As[buf][kk][ty * 8];
            *(float4*)&a[4] = *(const float4*)&As[buf][kk][ty * 8 + 4];
            *(float4*)&b[0] = *(const float4*)&Bs[buf][kk][tx * 8];
            *(float4*)&b[4] = *(const float4*)&Bs[buf][kk][tx * 8 + 4];
#pragma unroll
            for (int i = 0; i < 8; i++)
#pragma unroll
                for (int j = 0; j < 8; j++) acc[i][j] += a[i] * b[j];
        }
        if (kt + 1 < nk) {
            int nb = buf ^ 1;
#pragma unroll
            for (int q = 0; q < 4; q++) {
                As[nb][q * 4 + 0][tid] = aR[q].x; As[nb][q * 4 + 1][tid] = aR[q].y;
                As[nb][q * 4 + 2][tid] = aR[q].z; As[nb][q * 4 + 3][tid] = aR[q].w;
            }
            Bs[nb][bq0 * 4 + 0][bcol0] = bR[0].x; Bs[nb][bq0 * 4 + 1][bcol0] = bR[0].y;
            Bs[nb][bq0 * 4 + 2][bcol0] = bR[0].z; Bs[nb][bq0 * 4 + 3][bcol0] = bR[0].w;
            Bs[nb][bq1 * 4 + 0][bcol1] = bR[1].x; Bs[nb][bq1 * 4 + 1][bcol1] = bR[1].y;
            Bs[nb][bq1 * 4 + 2][bcol1] = bR[1].z; Bs[nb][bq1 * 4 + 3][bcol1] = bR[1].w;
            __syncthreads();
        }
    }

    // --- epilogue ---
    int col = bn + tx * 8;
    float bz[8];
#pragma unroll
    for (int j = 0; j < 8; j++) bz[j] = bias[col + j];
#pragma unroll
    for (int i = 0; i < 8; i++) {
        int row = bm + ty * 8 + i;
        float v[8];
#pragma unroll
        for (int j = 0; j < 8; j++) {
            v[j] = acc[i][j] + bz[j];
            if (EPI == 1) v[j] = 0.5f * v[j] * (1.f + erff(v[j] * 0.70710678118654752f));
        }
        if (EPI == 2) {
            float4 r0 = *(const float4*)&Res[(size_t)row * N + col];
            float4 r1 = *(const float4*)&Res[(size_t)row * N + col + 4];
            v[0] += r0.x; v[1] += r0.y; v[2] += r0.z; v[3] += r0.w;
            v[4] += r1.x; v[5] += r1.y; v[6] += r1.z; v[7] += r1.w;
        }
        *(float4*)&C[(size_t)row * N + col]     = make_float4(v[0], v[1], v[2], v[3]);
        *(float4*)&C[(size_t)row * N + col + 4] = make_float4(v[4], v[5], v[6], v[7]);
    }
}

// ---------------------------------------------------------------------------
// Attention per (window, head). One thread = one query row, flash-style
// online softmax with rare rescale. K/V staged in 64KB dynamic smem.
// ---------------------------------------------------------------------------
__global__ __launch_bounds__(256) void attn_kernel(
    const float* __restrict__ QKV, const float* __restrict__ biasT,
    float* __restrict__ O, int shifted) {
    extern __shared__ float sm[];
    float* Ks = sm;
    float* Vs = sm + LWIN * HDD;
    unsigned char* lbl = (unsigned char*)(Vs + LWIN * HDD);
    int n = blockIdx.x, h = blockIdx.y;
    int tid = threadIdx.x;
    {
        int r0 = tid >> 5, d = tid & 31;
        for (int pass = 0; pass < 32; pass++) {
            int r = (pass << 3) + r0;
            size_t base = (size_t)((n << 8) + r) * NQKV + h * HDD;
            Ks[r * HDD + d] = QKV[base + CCH + d];
            Vs[r * HDD + d] = QKV[base + 2 * CCH + d];
        }
    }
    int p = tid;
    if (shifted) {
        int rr = n & 63;
        int gd = ((rr >> 4) << 2) + (p >> 6);
        int gh = (((rr >> 2) & 3) << 3) + ((p >> 3) & 7);
        int gw = ((rr & 3) << 3) + (p & 7);
        lbl[p] = (unsigned char)(((gd < 2) ? 4 : 0) + ((gh < 4) ? 2 : 0) + ((gw < 4) ? 1 : 0));
    }
    __syncthreads();
    float q[HDD];
    {
        const float4* qp = (const float4*)(QKV + (size_t)((n << 8) + p) * NQKV + h * HDD);
#pragma unroll
        for (int i = 0; i < 8; i++) {
            float4 v = qp[i];
            q[i * 4] = v.x; q[i * 4 + 1] = v.y; q[i * 4 + 2] = v.z; q[i * 4 + 3] = v.w;
        }
    }
    float o[HDD];
#pragma unroll
    for (int d = 0; d < HDD; d++) o[d] = 0.f;
    float m = -3.0e38f, l = 0.f;
    const float* bT = biasT + (h << 16) + p;
    int myl = shifted ? (int)lbl[p] : 0;
    for (int k = 0; k < LWIN; k++) {
        if (shifted && (int)lbl[k] != myl) continue;   // exact exp(-inf)=0
        const float* kr = Ks + k * HDD;
        float s = 0.f;
#pragma unroll
        for (int d = 0; d < HDD; d++) s += q[d] * kr[d];
        s = s * ASCALE + bT[k << 8];
        const float* vr = Vs + k * HDD;
        if (s <= m) {
            float px = __expf(s - m);
            l += px;
#pragma unroll
            for (int d = 0; d < HDD; d++) o[d] += px * vr[d];
        } else {
            float c = __expf(m - s);
            l = l * c + 1.f;
#pragma unroll
            for (int d = 0; d < HDD; d++) o[d] = o[d] * c + vr[d];
            m = s;
        }
    }
    float inv = 1.f / l;
    float4* op = (float4*)(O + (size_t)((n << 8) + p) * CCH + h * HDD);
#pragma unroll
    for (int i = 0; i < 8; i++) {
        float4 v;
        v.x = o[i * 4] * inv; v.y = o[i * 4 + 1] * inv;
        v.z = o[i * 4 + 2] * inv; v.w = o[i * 4 + 3] * inv;
        op[i] = v;
    }
}

// ---------------------------------------------------------------------------
// Scatter proj output back to token-major with inverse shift, add residual.
// ---------------------------------------------------------------------------
__global__ __launch_bounds__(256) void scatter_add(
    const float* __restrict__ P, float* __restrict__ X, int shifted) {
    int idx = blockIdx.x * 256 + threadIdx.x;  // NTOK*CCH
    int wt = idx / CCH, c = idx - wt * CCH;
    int src = wt_to_src(wt, shifted);
    X[(size_t)src * CCH + c] += P[idx];
}

// ---------------------------------------------------------------------------
extern "C" void kernel_launch(void* const* d_in, const int* in_sizes, int n_in,
                              void* d_out, int out_size) {
    const float* x      = (const float*)d_in[0];
    const float* ln1_w  = (const float*)d_in[1];
    const float* ln1_b  = (const float*)d_in[2];
    const float* qkv_w  = (const float*)d_in[3];
    const float* qkv_b  = (const float*)d_in[4];
    const float* rpb    = (const float*)d_in[5];
    const float* proj_w = (const float*)d_in[6];
    const float* proj_b = (const float*)d_in[7];
    const float* ln2_w  = (const float*)d_in[8];
    const float* ln2_b  = (const float*)d_in[9];
    const float* fc1_w  = (const float*)d_in[10];
    const float* fc1_b  = (const float*)d_in[11];
    const float* fc2_w  = (const float*)d_in[12];
    const float* fc2_b  = (const float*)d_in[13];
    const int*   rpi    = (const int*)d_in[14];
    float* out = (float*)d_out;

    float *pX, *pH, *pQ, *pO, *pP, *pH2, *pM, *pB;
    cudaGetSymbolAddress((void**)&pX,  g_X);
    cudaGetSymbolAddress((void**)&pH,  g_Hb);
    cudaGetSymbolAddress((void**)&pQ,  g_QKV);
    cudaGetSymbolAddress((void**)&pO,  g_O);
    cudaGetSymbolAddress((void**)&pP,  g_P);
    cudaGetSymbolAddress((void**)&pH2, g_H2);
    cudaGetSymbolAddress((void**)&pM,  g_M);
    cudaGetSymbolAddress((void**)&pB,  g_biasT);

    const int ATTN_SMEM = 2 * LWIN * HDD * 4 + LWIN;  // 65792
    cudaFuncSetAttribute(attn_kernel, cudaFuncAttributeMaxDynamicSharedMemorySize,
                         ATTN_SMEM);

    dim3 tpb(32, 32);
    transpose_in<<<dim3(512, 6, 2), tpb>>>(x, pX);
    bias_gather<<<(2 * NHD * 65536) / 256, 256>>>(rpb, rpi, pB);

    for (int i = 0; i < 2; i++) {
        int sh = i;  // layer 1 shifted
        ln_kernel<<<NTOK / 8, 256>>>(pX, ln1_w + i * CCH, ln1_b + i * CCH, pH, sh ? 2 : 1);
        gemm_kernel<0><<<dim3(NQKV / 64, NTOK / 128), 128>>>(
            pH, qkv_w + (size_t)i * NQKV * CCH, qkv_b + i * NQKV, nullptr, pQ,
            NTOK, NQKV, CCH);
        attn_kernel<<<dim3(NWIN, NHD), 256, ATTN_SMEM>>>(
            pQ, pB + (size_t)i * NHD * 65536, pO, sh);
        gemm_kernel<0><<<dim3(CCH / 64, NTOK / 128), 128>>>(
            pO, proj_w + (size_t)i * CCH * CCH, proj_b + i * CCH, nullptr, pP,
            NTOK, CCH, CCH);
        scatter_add<<<(NTOK * CCH) / 256, 256>>>(pP, pX, sh);
        ln_kernel<<<NTOK / 8, 256>>>(pX, ln2_w + i * CCH, ln2_b + i * CCH, pH2, 0);
        gemm_kernel<1><<<dim3(HIDN / 64, NTOK / 128), 128>>>(
            pH2, fc1_w + (size_t)i * HIDN * CCH, fc1_b + i * HIDN, nullptr, pM,
            NTOK, HIDN, CCH);
        gemm_kernel<2><<<dim3(CCH / 64, NTOK / 128), 128>>>(
            pM, fc2_w + (size_t)i * CCH * HIDN, fc2_b + i * CCH, pX, pX,
            NTOK, CCH, HIDN);
    }
    transpose_out<<<dim3(512, 6, 2), tpb>>>(pX, out);
}

// round 4
// speedup vs baseline: 1.4706x; 1.4130x over previous
#include <cuda_runtime.h>
#include <cuda_bf16.h>
#include <math.h>
#include <cstdint>

// ---------------------------------------------------------------------------
// SwinLayer: B=2, C=192, NH=6, HD=32, D=16,H=32,W=32, window (4,8,8), L=256
// DEPTH=2, HID=768.  GEMMs on mma.sync bf16 via split-bf16 (3-term) trick.
// (tcgen05 unavailable: harness targets compute_100, not sm_100a)
// ---------------------------------------------------------------------------

#define NTOK 32768
#define CCH 192
#define NQKV 576
#define HIDN 768
#define NWIN 128
#define LWIN 256
#define NHD 6
#define HDD 32
#define ASCALE 0.17677669529663687f

#define K3C (3*CCH)      // 576
#define K3H (3*HIDN)     // 2304
#define BM 128
#define BN 64
#define BK 32            // bf16 elems per chunk; 64B rows, 4x16B chunks
#define STAGES 3

// ---------------- scratch (device globals; allocation-free rule) -----------
__device__ float g_X   [NTOK*CCH];
__device__ float g_QKV [NTOK*NQKV];
__device__ float g_P   [NTOK*CCH];
__device__ float g_biasT[2*NHD*LWIN*LWIN];
__device__ __nv_bfloat16 g_Hs [NTOK*K3C];
__device__ __nv_bfloat16 g_Os [NTOK*K3C];
__device__ __nv_bfloat16 g_H2s[NTOK*K3C];
__device__ __nv_bfloat16 g_Ms [(size_t)NTOK*K3H];
__device__ __nv_bfloat16 g_Wq [2*NQKV*K3C];
__device__ __nv_bfloat16 g_Wp [2*CCH*K3C];
__device__ __nv_bfloat16 g_W1 [2*HIDN*K3C];
__device__ __nv_bfloat16 g_W2 [2*CCH*K3H];

// ---------------- helpers ---------------------------------------------------
__device__ __forceinline__ uint32_t smem_u32(const void* p) {
    uint32_t a;
    asm("{ .reg .u64 t; cvta.to.shared.u64 t, %1; cvt.u32.u64 %0, t; }" : "=r"(a) : "l"(p));
    return a;
}
__device__ __forceinline__ void cp16(uint32_t dst, const void* src) {
    asm volatile("cp.async.cg.shared.global [%0], [%1], 16;" :: "r"(dst), "l"(src) : "memory");
}
#define CP_COMMIT() asm volatile("cp.async.commit_group;" ::: "memory")
#define CP_WAIT1()  asm volatile("cp.async.wait_group 1;" ::: "memory")
__device__ __forceinline__ void ldsm4(uint32_t& r0, uint32_t& r1, uint32_t& r2,
                                      uint32_t& r3, uint32_t addr) {
    asm volatile("ldmatrix.sync.aligned.m8n8.x4.shared.b16 {%0,%1,%2,%3}, [%4];"
                 : "=r"(r0), "=r"(r1), "=r"(r2), "=r"(r3) : "r"(addr));
}
__device__ __forceinline__ void mma16816(float* c, const uint32_t* a, const uint32_t* b) {
    asm volatile(
        "mma.sync.aligned.m16n8k16.row.col.f32.bf16.bf16.f32 "
        "{%0,%1,%2,%3}, {%4,%5,%6,%7}, {%8,%9}, {%0,%1,%2,%3};"
        : "+f"(c[0]), "+f"(c[1]), "+f"(c[2]), "+f"(c[3])
        : "r"(a[0]), "r"(a[1]), "r"(a[2]), "r"(a[3]), "r"(b[0]), "r"(b[1]));
}

// window-token -> original token index
__device__ __forceinline__ int wt_to_src(int wt, int shifted) {
    int n = wt >> 8, p = wt & 255;
    int bb = n >> 6, r = n & 63;
    int gd = ((r >> 4) << 2) + (p >> 6);
    int gh = (((r >> 2) & 3) << 3) + ((p >> 3) & 7);
    int gw = ((r & 3) << 3) + (p & 7);
    if (shifted) { gd = (gd + 14) & 15; gh = (gh + 28) & 31; gw = (gw + 28) & 31; }
    return ((bb * 16 + gd) * 32 + gh) * 32 + gw;
}
__device__ __forceinline__ void split_bf16(float x, __nv_bfloat16& hi, __nv_bfloat16& lo) {
    hi = __float2bfloat16(x);
    lo = __float2bfloat16(x - __bfloat162float(hi));
}

// ---------------------------------------------------------------------------
__global__ void transpose_in(const float* __restrict__ x, float* __restrict__ X) {
    __shared__ float t[32][33];
    int b = blockIdx.z;
    int s0 = blockIdx.x * 32, c0 = blockIdx.y * 32;
    t[threadIdx.y][threadIdx.x] =
        x[((size_t)(b * CCH + c0 + threadIdx.y)) * 16384 + s0 + threadIdx.x];
    __syncthreads();
    X[((size_t)(b * 16384 + s0 + threadIdx.y)) * CCH + c0 + threadIdx.x] =
        t[threadIdx.x][threadIdx.y];
}
__global__ void transpose_out(const float* __restrict__ X, float* __restrict__ out) {
    __shared__ float t[32][33];
    int b = blockIdx.z;
    int s0 = blockIdx.x * 32, c0 = blockIdx.y * 32;
    t[threadIdx.y][threadIdx.x] =
        X[((size_t)(b * 16384 + s0 + threadIdx.y)) * CCH + c0 + threadIdx.x];
    __syncthreads();
    out[((size_t)(b * CCH + c0 + threadIdx.y)) * 16384 + s0 + threadIdx.x] =
        t[threadIdx.x][threadIdx.y];
}

__global__ void bias_gather(const float* __restrict__ rpb, const int* __restrict__ rpi,
                            float* __restrict__ biasT) {
    int idx = blockIdx.x * 256 + threadIdx.x;
    if (idx >= 2 * NHD * 65536) return;
    int lh = idx >> 16;
    int kk = idx & 65535;
    int p = kk & 255, k = kk >> 8;
    biasT[idx] = rpb[lh * 1575 + rpi[p * 256 + k]];
}

// weight split: W[N,K] f32 -> W'[N,3K] bf16 as [hi|hi|lo]
__global__ void wsplit(const float* __restrict__ W, __nv_bfloat16* __restrict__ Ws,
                       int N, int K) {
    int idx = blockIdx.x * 256 + threadIdx.x;
    if (idx >= N * K) return;
    int n = idx / K, k = idx - n * K;
    __nv_bfloat16 hi, lo;
    split_bf16(W[idx], hi, lo);
    size_t base = (size_t)n * 3 * K;
    Ws[base + k] = hi; Ws[base + K + k] = hi; Ws[base + 2 * K + k] = lo;
}

// ---------------------------------------------------------------------------
// LayerNorm -> split bf16 out [hi|lo|hi].
// ---------------------------------------------------------------------------
__global__ __launch_bounds__(256) void ln_kernel(
    const float* __restrict__ X, const float* __restrict__ w,
    const float* __restrict__ b, __nv_bfloat16* __restrict__ Out, int mode) {
    int warp = threadIdx.x >> 5, lane = threadIdx.x & 31;
    int wt = blockIdx.x * 8 + warp;
    int src = (mode == 0) ? wt : wt_to_src(wt, mode == 2);
    const float* xp = X + (size_t)src * CCH;
    float v[6];
    float s = 0.f;
#pragma unroll
    for (int i = 0; i < 6; i++) { v[i] = xp[lane + 32 * i]; s += v[i]; }
#pragma unroll
    for (int off = 16; off > 0; off >>= 1) s += __shfl_xor_sync(0xffffffffu, s, off);
    float mu = s * (1.f / CCH);
    float s2 = 0.f;
#pragma unroll
    for (int i = 0; i < 6; i++) { float d = v[i] - mu; s2 += d * d; }
#pragma unroll
    for (int off = 16; off > 0; off >>= 1) s2 += __shfl_xor_sync(0xffffffffu, s2, off);
    float inv = rsqrtf(s2 * (1.f / CCH) + 1e-5f);
    __nv_bfloat16* op = Out + (size_t)wt * K3C;
#pragma unroll
    for (int i = 0; i < 6; i++) {
        int c = lane + 32 * i;
        float y = (v[i] - mu) * inv * w[c] + b[c];
        __nv_bfloat16 hi, lo;
        split_bf16(y, hi, lo);
        op[c] = hi; op[CCH + c] = lo; op[2 * CCH + c] = hi;
    }
}

// ---------------------------------------------------------------------------
// Tensor-core GEMM (mma.sync bf16): C[M,N] = A'[M,K3] @ W'[N,K3]^T + bias.
// EPI 0: f32 out. 1: GELU -> split bf16 (stride 3N). 2: f32 out + Res.
// 128x64 tile, 4 warps (2Mx2N), warp tile 64x32, BK=32, 3-stage cp.async.
// Smem rows 64B, 16B chunks XOR-swizzled by (row>>1)&3: conflict-free
// cp.async fill and ldmatrix reads.
// ---------------------------------------------------------------------------
#define SWC(row, ch) (((row) * 64) + ((((ch) ^ (((row) >> 1) & 3))) << 4))

template <int EPI>
__global__ __launch_bounds__(128) void gemm_mma(
    const __nv_bfloat16* __restrict__ A, const __nv_bfloat16* __restrict__ Wt,
    const float* __restrict__ bias, const float* __restrict__ Res,
    void* __restrict__ Cout, int M, int N, int K3) {
    extern __shared__ char smem[];
    uint32_t sAb = smem_u32(smem);              // STAGES * 8192
    uint32_t sBb = sAb + STAGES * (BM * 64);    // STAGES * 4096
    int tid = threadIdx.x, lane = tid & 31, wid = tid >> 5;
    int wm = wid >> 1, wn = wid & 1;            // 2x2 warp grid
    int bm = blockIdx.x * BM, bn = blockIdx.y * BN;

    // ldmatrix per-lane invariants
    uint32_t rowA[4], swA[4];
#pragma unroll
    for (int mt = 0; mt < 4; mt++) {
        int r = wm * 64 + mt * 16 + (lane & 15);
        rowA[mt] = r * 64; swA[mt] = (r >> 1) & 3;
    }
    uint32_t hiA = lane >> 4;                   // k-chunk select for A
    uint32_t rowB[2], swB[2];
#pragma unroll
    for (int pr = 0; pr < 2; pr++) {
        int r = wn * 32 + pr * 16 + (lane & 7) + ((lane >> 4) & 1) * 8;
        rowB[pr] = r * 64; swB[pr] = (r >> 1) & 3;
    }
    uint32_t hiB = (lane >> 3) & 1;

    float acc[4][4][4];
#pragma unroll
    for (int i = 0; i < 4; i++)
#pragma unroll
        for (int j = 0; j < 4; j++)
#pragma unroll
            for (int q = 0; q < 4; q++) acc[i][j][q] = 0.f;

    const int NC = K3 / BK;

    // stage fill: A 512x16B (4 iters), B 256x16B (2 iters)
#define LOAD_STAGE(S, CIDX) do {                                              \
        int kb = (CIDX) * BK;                                                 \
        uint32_t sa = sAb + (S) * (BM * 64);                                  \
        uint32_t sb = sBb + (S) * (BN * 64);                                  \
        _Pragma("unroll")                                                     \
        for (int it = 0; it < 4; it++) {                                      \
            int idx = tid + it * 128;                                         \
            int r = idx >> 2, ch = idx & 3;                                   \
            cp16(sa + SWC(r, ch), A + (size_t)(bm + r) * K3 + kb + ch * 8);   \
        }                                                                     \
        _Pragma("unroll")                                                     \
        for (int it = 0; it < 2; it++) {                                      \
            int idx = tid + it * 128;                                         \
            int r = idx >> 2, ch = idx & 3;                                   \
            cp16(sb + SWC(r, ch), Wt + (size_t)(bn + r) * K3 + kb + ch * 8);  \
        }                                                                     \
    } while (0)

    LOAD_STAGE(0, 0); CP_COMMIT();
    LOAD_STAGE(1, 1); CP_COMMIT();

    for (int c = 0; c < NC; c++) {
        int s = c % STAGES;
        CP_WAIT1();
        __syncthreads();
        uint32_t sa = sAb + s * (BM * 64);
        uint32_t sb = sBb + s * (BN * 64);
#pragma unroll
        for (int ks = 0; ks < 2; ks++) {
            uint32_t a[4][4], b[4][2];
#pragma unroll
            for (int mt = 0; mt < 4; mt++)
                ldsm4(a[mt][0], a[mt][1], a[mt][2], a[mt][3],
                      sa + rowA[mt] + (((2 * ks + hiA) ^ swA[mt]) << 4));
#pragma unroll
            for (int pr = 0; pr < 2; pr++)
                ldsm4(b[pr * 2][0], b[pr * 2][1], b[pr * 2 + 1][0], b[pr * 2 + 1][1],
                      sb + rowB[pr] + (((2 * ks + hiB) ^ swB[pr]) << 4));
#pragma unroll
            for (int mt = 0; mt < 4; mt++)
#pragma unroll
                for (int nt = 0; nt < 4; nt++)
                    mma16816(acc[mt][nt], a[mt], b[nt]);
        }
        if (c + 2 < NC) LOAD_STAGE((c + 2) % STAGES, c + 2);
        CP_COMMIT();   // exactly one group per iteration (maybe empty)
    }

    // ---- epilogue ----
#pragma unroll
    for (int mt = 0; mt < 4; mt++) {
#pragma unroll
        for (int nt = 0; nt < 4; nt++) {
            int r0 = bm + wm * 64 + mt * 16 + (lane >> 2);
            int col = bn + wn * 32 + nt * 8 + (lane & 3) * 2;
            float b0 = bias[col], b1 = bias[col + 1];
            float v00 = acc[mt][nt][0] + b0, v01 = acc[mt][nt][1] + b1;
            float v10 = acc[mt][nt][2] + b0, v11 = acc[mt][nt][3] + b1;
            if (EPI == 0 || EPI == 2) {
                float* C = (float*)Cout;
                size_t o0 = (size_t)r0 * N + col;
                size_t o1 = (size_t)(r0 + 8) * N + col;
                if (EPI == 2) {
                    float2 q0 = *(const float2*)&Res[o0];
                    float2 q1 = *(const float2*)&Res[o1];
                    v00 += q0.x; v01 += q0.y; v10 += q1.x; v11 += q1.y;
                }
                *(float2*)&C[o0] = make_float2(v00, v01);
                *(float2*)&C[o1] = make_float2(v10, v11);
            } else {
                v00 = 0.5f * v00 * (1.f + erff(v00 * 0.70710678118654752f));
                v01 = 0.5f * v01 * (1.f + erff(v01 * 0.70710678118654752f));
                v10 = 0.5f * v10 * (1.f + erff(v10 * 0.70710678118654752f));
                v11 = 0.5f * v11 * (1.f + erff(v11 * 0.70710678118654752f));
                __nv_bfloat16 h0, l0, h1, l1, h2, l2, h3, l3;
                split_bf16(v00, h0, l0); split_bf16(v01, h1, l1);
                split_bf16(v10, h2, l2); split_bf16(v11, h3, l3);
                uint32_t ph0 = ((uint32_t)__bfloat16_as_ushort(h1) << 16) | __bfloat16_as_ushort(h0);
                uint32_t pl0 = ((uint32_t)__bfloat16_as_ushort(l1) << 16) | __bfloat16_as_ushort(l0);
                uint32_t ph1 = ((uint32_t)__bfloat16_as_ushort(h3) << 16) | __bfloat16_as_ushort(h2);
                uint32_t pl1 = ((uint32_t)__bfloat16_as_ushort(l3) << 16) | __bfloat16_as_ushort(l2);
                __nv_bfloat16* C = (__nv_bfloat16*)Cout;
                size_t rb0 = (size_t)r0 * 3 * N;
                size_t rb1 = (size_t)(r0 + 8) * 3 * N;
                *(uint32_t*)&C[rb0 + col]         = ph0;
                *(uint32_t*)&C[rb0 + N + col]     = pl0;
                *(uint32_t*)&C[rb0 + 2 * N + col] = ph0;
                *(uint32_t*)&C[rb1 + col]         = ph1;
                *(uint32_t*)&C[rb1 + N + col]     = pl1;
                *(uint32_t*)&C[rb1 + 2 * N + col] = ph1;
            }
        }
    }
}

// ---------------------------------------------------------------------------
// Attention per (window, head). f32 in (QKV), split-bf16 out.
// ---------------------------------------------------------------------------
__global__ __launch_bounds__(256) void attn_kernel(
    const float* __restrict__ QKV, const float* __restrict__ biasT,
    __nv_bfloat16* __restrict__ O, int shifted) {
    extern __shared__ float sm[];
    float* Ks = sm;
    float* Vs = sm + LWIN * HDD;
    unsigned char* lbl = (unsigned char*)(Vs + LWIN * HDD);
    int n = blockIdx.x, h = blockIdx.y;
    int tid = threadIdx.x;
    {
        int r0 = tid >> 5, dd = tid & 31;
        for (int pass = 0; pass < 32; pass++) {
            int r = (pass << 3) + r0;
            size_t basep = (size_t)((n << 8) + r) * NQKV + h * HDD;
            Ks[r * HDD + dd] = QKV[basep + CCH + dd];
            Vs[r * HDD + dd] = QKV[basep + 2 * CCH + dd];
        }
    }
    int p = tid;
    if (shifted) {
        int rr = n & 63;
        int gd = ((rr >> 4) << 2) + (p >> 6);
        int gh = (((rr >> 2) & 3) << 3) + ((p >> 3) & 7);
        int gw = ((rr & 3) << 3) + (p & 7);
        lbl[p] = (unsigned char)(((gd < 2) ? 4 : 0) + ((gh < 4) ? 2 : 0) + ((gw < 4) ? 1 : 0));
    }
    __syncthreads();
    float q[HDD];
    {
        const float4* qp = (const float4*)(QKV + (size_t)((n << 8) + p) * NQKV + h * HDD);
#pragma unroll
        for (int i = 0; i < 8; i++) {
            float4 v = qp[i];
            q[i * 4] = v.x; q[i * 4 + 1] = v.y; q[i * 4 + 2] = v.z; q[i * 4 + 3] = v.w;
        }
    }
    float o[HDD];
#pragma unroll
    for (int dd = 0; dd < HDD; dd++) o[dd] = 0.f;
    float m = -3.0e38f, l = 0.f;
    const float* bT = biasT + (h << 16) + p;
    int myl = shifted ? (int)lbl[p] : 0;
    for (int k = 0; k < LWIN; k++) {
        if (shifted && (int)lbl[k] != myl) continue;
        const float* kr = Ks + k * HDD;
        float s = 0.f;
#pragma unroll
        for (int dd = 0; dd < HDD; dd++) s += q[dd] * kr[dd];
        s = s * ASCALE + bT[k << 8];
        const float* vr = Vs + k * HDD;
        if (s <= m) {
            float px = __expf(s - m);
            l += px;
#pragma unroll
            for (int dd = 0; dd < HDD; dd++) o[dd] += px * vr[dd];
        } else {
            float c = __expf(m - s);
            l = l * c + 1.f;
#pragma unroll
            for (int dd = 0; dd < HDD; dd++) o[dd] = o[dd] * c + vr[dd];
            m = s;
        }
    }
    float inv = 1.f / l;
    __nv_bfloat16* op = O + (size_t)((n << 8) + p) * K3C + h * HDD;
#pragma unroll
    for (int dd = 0; dd < HDD; dd++) {
        float y = o[dd] * inv;
        __nv_bfloat16 hi, lo;
        split_bf16(y, hi, lo);
        op[dd] = hi; op[CCH + dd] = lo; op[2 * CCH + dd] = hi;
    }
}

// ---------------------------------------------------------------------------
__global__ __launch_bounds__(256) void scatter_add(
    const float* __restrict__ Pp, float* __restrict__ X, int shifted) {
    int idx = blockIdx.x * 256 + threadIdx.x;
    int wt = idx / CCH, c = idx - wt * CCH;
    int src = wt_to_src(wt, shifted);
    X[(size_t)src * CCH + c] += Pp[idx];
}

// ---------------------------------------------------------------------------
extern "C" void kernel_launch(void* const* d_in, const int* in_sizes, int n_in,
                              void* d_out, int out_size) {
    const float* x      = (const float*)d_in[0];
    const float* ln1_w  = (const float*)d_in[1];
    const float* ln1_b  = (const float*)d_in[2];
    const float* qkv_w  = (const float*)d_in[3];
    const float* qkv_b  = (const float*)d_in[4];
    const float* rpb    = (const float*)d_in[5];
    const float* proj_w = (const float*)d_in[6];
    const float* proj_b = (const float*)d_in[7];
    const float* ln2_w  = (const float*)d_in[8];
    const float* ln2_b  = (const float*)d_in[9];
    const float* fc1_w  = (const float*)d_in[10];
    const float* fc1_b  = (const float*)d_in[11];
    const float* fc2_w  = (const float*)d_in[12];
    const float* fc2_b  = (const float*)d_in[13];
    const int*   rpi    = (const int*)d_in[14];
    float* out = (float*)d_out;

    float *pX, *pQ, *pP, *pB;
    __nv_bfloat16 *pHs, *pOs, *pH2s, *pMs, *pWq, *pWp, *pW1, *pW2;
    cudaGetSymbolAddress((void**)&pX,  g_X);
    cudaGetSymbolAddress((void**)&pQ,  g_QKV);
    cudaGetSymbolAddress((void**)&pP,  g_P);
    cudaGetSymbolAddress((void**)&pB,  g_biasT);
    cudaGetSymbolAddress((void**)&pHs, g_Hs);
    cudaGetSymbolAddress((void**)&pOs, g_Os);
    cudaGetSymbolAddress((void**)&pH2s, g_H2s);
    cudaGetSymbolAddress((void**)&pMs, g_Ms);
    cudaGetSymbolAddress((void**)&pWq, g_Wq);
    cudaGetSymbolAddress((void**)&pWp, g_Wp);
    cudaGetSymbolAddress((void**)&pW1, g_W1);
    cudaGetSymbolAddress((void**)&pW2, g_W2);

    const int ATTN_SMEM = 2 * LWIN * HDD * 4 + LWIN;
    cudaFuncSetAttribute(attn_kernel, cudaFuncAttributeMaxDynamicSharedMemorySize, ATTN_SMEM);
    const int GSMEM = STAGES * (BM * 64 + BN * 64);  // 36864
    cudaFuncSetAttribute(gemm_mma<0>, cudaFuncAttributeMaxDynamicSharedMemorySize, GSMEM);
    cudaFuncSetAttribute(gemm_mma<1>, cudaFuncAttributeMaxDynamicSharedMemorySize, GSMEM);
    cudaFuncSetAttribute(gemm_mma<2>, cudaFuncAttributeMaxDynamicSharedMemorySize, GSMEM);

    dim3 tpb(32, 32);
    transpose_in<<<dim3(512, 6, 2), tpb>>>(x, pX);
    bias_gather<<<(2 * NHD * 65536) / 256, 256>>>(rpb, rpi, pB);
    for (int i = 0; i < 2; i++) {
        wsplit<<<(NQKV * CCH + 255) / 256, 256>>>(qkv_w + (size_t)i * NQKV * CCH,
                                                  pWq + (size_t)i * NQKV * K3C, NQKV, CCH);
        wsplit<<<(CCH * CCH + 255) / 256, 256>>>(proj_w + (size_t)i * CCH * CCH,
                                                 pWp + (size_t)i * CCH * K3C, CCH, CCH);
        wsplit<<<(HIDN * CCH + 255) / 256, 256>>>(fc1_w + (size_t)i * HIDN * CCH,
                                                  pW1 + (size_t)i * HIDN * K3C, HIDN, CCH);
        wsplit<<<(CCH * HIDN + 255) / 256, 256>>>(fc2_w + (size_t)i * CCH * HIDN,
                                                  pW2 + (size_t)i * CCH * K3H, CCH, HIDN);
    }

    for (int i = 0; i < 2; i++) {
        int sh = i;
        ln_kernel<<<NTOK / 8, 256>>>(pX, ln1_w + i * CCH, ln1_b + i * CCH, pHs, sh ? 2 : 1);
        gemm_mma<0><<<dim3(NTOK / BM, NQKV / BN), 128, GSMEM>>>(
            pHs, pWq + (size_t)i * NQKV * K3C, qkv_b + i * NQKV, nullptr, pQ,
            NTOK, NQKV, K3C);
        attn_kernel<<<dim3(NWIN, NHD), 256, ATTN_SMEM>>>(
            pQ, pB + (size_t)i * NHD * 65536, pOs, sh);
        gemm_mma<0><<<dim3(NTOK / BM, CCH / BN), 128, GSMEM>>>(
            pOs, pWp + (size_t)i * CCH * K3C, proj_b + i * CCH, nullptr, pP,
            NTOK, CCH, K3C);
        scatter_add<<<(NTOK * CCH) / 256, 256>>>(pP, pX, sh);
        ln_kernel<<<NTOK / 8, 256>>>(pX, ln2_w + i * CCH, ln2_b + i * CCH, pH2s, 0);
        gemm_mma<1><<<dim3(NTOK / BM, HIDN / BN), 128, GSMEM>>>(
            pH2s, pW1 + (size_t)i * HIDN * K3C, fc1_b + i * HIDN, nullptr, pMs,
            NTOK, HIDN, K3C);
        gemm_mma<2><<<dim3(NTOK / BM, CCH / BN), 128, GSMEM>>>(
            pMs, pW2 + (size_t)i * CCH * K3H, fc2_b + i * CCH, pX, pX,
            NTOK, CCH, K3H);
    }
    transpose_out<<<dim3(512, 6, 2), tpb>>>(pX, out);
}